// round 16
// baseline (speedup 1.0000x reference)
#include <cuda_runtime.h>
#include <cuda_bf16.h>
#include <math.h>
#include <stdint.h>

#define BB 16
#define NN 8192
#define DD 512
#define HH 8
#define KSEED 4
#define OO 32            // KSEED*HH, o = i*8 + h

// ---- scratch (no allocations allowed; __device__ globals) ----
__device__ float g_P[OO * DD];
__device__ float g_c0[OO];
__device__ float g_S[(size_t)BB * OO * NN];        // exp(scores)
__device__ float g_sum[BB * OO];                   // sum of exp (atomic)
__device__ float g_y[BB * OO * DD];                // UNNORMALIZED pooled values (atomic)
__device__ float g_pre[BB * KSEED * DD];           // Wv-stage output (atomic)
__device__ float g_z[BB * KSEED * DD];             // Wo-stage output (atomic)

// ---- warp-level bf16 MMA ----
__device__ __forceinline__ void mma_bf16(float* c, const unsigned* a,
                                         unsigned b0, unsigned b1) {
    asm volatile(
        "mma.sync.aligned.m16n8k16.row.col.f32.bf16.bf16.f32 "
        "{%0,%1,%2,%3}, {%4,%5,%6,%7}, {%8,%9}, {%0,%1,%2,%3};"
        : "+f"(c[0]), "+f"(c[1]), "+f"(c[2]), "+f"(c[3])
        : "r"(a[0]), "r"(a[1]), "r"(a[2]), "r"(a[3]), "r"(b0), "r"(b1));
}

__device__ __forceinline__ void ldsm4t(unsigned& r0, unsigned& r1,
                                       unsigned& r2, unsigned& r3,
                                       const void* p) {
    uint32_t a = (uint32_t)__cvta_generic_to_shared(p);
    asm volatile(
        "ldmatrix.sync.aligned.m8n8.x4.trans.shared.b16 {%0,%1,%2,%3}, [%4];"
        : "=r"(r0), "=r"(r1), "=r"(r2), "=r"(r3) : "r"(a));
}

__device__ __forceinline__ void split2(float a, float b, unsigned& hi, unsigned& lo) {
    __nv_bfloat16 ha = __float2bfloat16_rn(a), hb = __float2bfloat16_rn(b);
    unsigned uh = (unsigned)__bfloat16_as_ushort(ha) |
                  ((unsigned)__bfloat16_as_ushort(hb) << 16);
    __nv_bfloat16 la = __float2bfloat16_rn(a - __bfloat162float(ha));
    __nv_bfloat16 lb = __float2bfloat16_rn(b - __bfloat162float(hb));
    unsigned ul = (unsigned)__bfloat16_as_ushort(la) |
                  ((unsigned)__bfloat16_as_ushort(lb) << 16);
    hi = uh; lo = ul;
}

// ---- K0 (fused): per head h, compute q-slice, then P and c0; zero accumulators ----
__global__ void k0_fused(const float* __restrict__ seed,
                         const float* __restrict__ Wq,
                         const float* __restrict__ bq,
                         const float* __restrict__ Wk,
                         const float* __restrict__ bk) {
    __shared__ float qsh[KSEED * 64];
    int h = blockIdx.x;
    int t = threadIdx.x;
    if (t < BB * OO) g_sum[t] = 0.f;
    {
        int gid = t + h * 512;
        float4 z4 = make_float4(0.f, 0.f, 0.f, 0.f);
        for (int z = gid; z < BB * OO * DD / 4; z += HH * 512)
            ((float4*)g_y)[z] = z4;
        for (int z = gid; z < BB * KSEED * DD / 4; z += HH * 512) {
            ((float4*)g_pre)[z] = z4;
            ((float4*)g_z)[z] = z4;
        }
    }
    if (t < KSEED * 64) {
        int i = t >> 6, d = t & 63;
        int g = h * 64 + d;
        const float4* w  = (const float4*)(Wq + (size_t)g * DD);
        const float4* sd = (const float4*)(seed + (size_t)i * DD);
        float acc = 0.f;
#pragma unroll 8
        for (int e4 = 0; e4 < DD / 4; e4++) {
            float4 a = w[e4], s4 = sd[e4];
            acc += a.x * s4.x + a.y * s4.y + a.z * s4.z + a.w * s4.w;
        }
        qsh[t] = acc + bq[g];
    }
    __syncthreads();
    int c = t;   // 0..511
    float acc[KSEED] = {0.f, 0.f, 0.f, 0.f};
#pragma unroll 8
    for (int d = 0; d < 64; d++) {
        float w = Wk[(size_t)(h * 64 + d) * DD + c];
#pragma unroll
        for (int i = 0; i < KSEED; i++) acc[i] += qsh[i * 64 + d] * w;
    }
#pragma unroll
    for (int i = 0; i < KSEED; i++)
        g_P[(size_t)(i * HH + h) * DD + c] = acc[i] * 0.125f;
    if (c < KSEED) {
        float a = 0.f;
#pragma unroll 8
        for (int d = 0; d < 64; d++) a += qsh[c * 64 + d] * bk[h * 64 + d];
        g_c0[c * HH + h] = a * 0.125f;
    }
}

// ============ K1: exp-scores + per-(b,o) partial sums (atomic) ============
#define XP 72   // padded row (bf16 elements) for X tile
#define SCP 132 // scratch row pad (floats)
__global__ __launch_bounds__(256) void k1_scores_mma(const float* __restrict__ X) {
    __shared__ __align__(16) __nv_bfloat16 Xhi[128 * XP];   // reused as scratch
    __shared__ __align__(16) __nv_bfloat16 Xlo[128 * XP];
    __shared__ __align__(16) __nv_bfloat16 Phi[OO * XP];
    __shared__ __align__(16) __nv_bfloat16 Plo[OO * XP];
    __shared__ float c0s[OO];

    int t = threadIdx.x, w = t >> 5, l = t & 31;
    int b = blockIdx.y;
    int nbase = blockIdx.x * 128;
    if (t < OO) c0s[t] = g_c0[t];

    float acc[4][4];
#pragma unroll
    for (int ot = 0; ot < 4; ot++)
#pragma unroll
        for (int j = 0; j < 4; j++) acc[ot][j] = 0.f;

    const float* Xb = X + ((size_t)b * NN + nbase) * DD;

    float4 xv[8], pv[2];
    auto load_stage = [&](int kc) {
        int cbase = kc * 64;
#pragma unroll
        for (int i = 0; i < 8; i++) {
            int idx = t + i * 256;
            int row = idx >> 4, q = idx & 15;
            xv[i] = *(const float4*)(Xb + (size_t)row * DD + cbase + q * 4);
        }
#pragma unroll
        for (int i = 0; i < 2; i++) {
            int idx = t + i * 256;
            int row = idx >> 4, q = idx & 15;
            pv[i] = *(const float4*)(g_P + (size_t)row * DD + cbase + q * 4);
        }
    };

    load_stage(0);

#pragma unroll 1
    for (int kc = 0; kc < 8; kc++) {
        __syncthreads();
#pragma unroll
        for (int i = 0; i < 8; i++) {
            int idx = t + i * 256;
            int row = idx >> 4, q = idx & 15;
            unsigned h0, l0, h1, l1;
            split2(xv[i].x, xv[i].y, h0, l0);
            split2(xv[i].z, xv[i].w, h1, l1);
            *(uint2*)(Xhi + row * XP + q * 4) = make_uint2(h0, h1);
            *(uint2*)(Xlo + row * XP + q * 4) = make_uint2(l0, l1);
        }
#pragma unroll
        for (int i = 0; i < 2; i++) {
            int idx = t + i * 256;
            int row = idx >> 4, q = idx & 15;
            unsigned h0, l0, h1, l1;
            split2(pv[i].x, pv[i].y, h0, l0);
            split2(pv[i].z, pv[i].w, h1, l1);
            *(uint2*)(Phi + row * XP + q * 4) = make_uint2(h0, h1);
            *(uint2*)(Plo + row * XP + q * 4) = make_uint2(l0, l1);
        }
        __syncthreads();

        if (kc + 1 < 8) load_stage(kc + 1);

#pragma unroll
        for (int ks = 0; ks < 4; ks++) {
            int ar = (w * 16 + (l >> 2)) * XP + ks * 16 + (l & 3) * 2;
            unsigned ah[4], al[4];
            ah[0] = *(const unsigned*)(Xhi + ar);
            ah[1] = *(const unsigned*)(Xhi + ar + 8 * XP);
            ah[2] = *(const unsigned*)(Xhi + ar + 8);
            ah[3] = *(const unsigned*)(Xhi + ar + 8 * XP + 8);
            al[0] = *(const unsigned*)(Xlo + ar);
            al[1] = *(const unsigned*)(Xlo + ar + 8 * XP);
            al[2] = *(const unsigned*)(Xlo + ar + 8);
            al[3] = *(const unsigned*)(Xlo + ar + 8 * XP + 8);
#pragma unroll
            for (int ot = 0; ot < 4; ot++) {
                int br = (ot * 8 + (l >> 2)) * XP + ks * 16 + (l & 3) * 2;
                unsigned bh0 = *(const unsigned*)(Phi + br);
                unsigned bh1 = *(const unsigned*)(Phi + br + 8);
                unsigned bl0 = *(const unsigned*)(Plo + br);
                unsigned bl1 = *(const unsigned*)(Plo + br + 8);
                mma_bf16(acc[ot], ah, bh0, bh1);
                mma_bf16(acc[ot], ah, bl0, bl1);
                mma_bf16(acc[ot], al, bh0, bh1);
            }
        }
    }

    // ---- epilogue: exp, store, block-reduce sums, atomic ----
    __syncthreads();
    float* scratch = (float*)Xhi;
    int row = w * 16 + (l >> 2);
#pragma unroll
    for (int ot = 0; ot < 4; ot++) {
        int colb = ot * 8 + 2 * (l & 3);
#pragma unroll
        for (int j = 0; j < 4; j++) {
            int col = colb + (j & 1);
            int r2  = row + 8 * (j >> 1);
            float e = __expf(acc[ot][j] + c0s[col]);
            g_S[((size_t)b * OO + col) * NN + nbase + r2] = e;
            scratch[col * SCP + r2] = e;
        }
    }
    __syncthreads();
    {
        int o = w * 4 + (l >> 3);
        int nstart = (l & 7) * 16;
        const float* sr = scratch + o * SCP + nstart;
        float ssum = 0.f;
#pragma unroll
        for (int k = 0; k < 16; k++) ssum += sr[k];
        ssum += __shfl_xor_sync(0xffffffffu, ssum, 1);
        ssum += __shfl_xor_sync(0xffffffffu, ssum, 2);
        ssum += __shfl_xor_sync(0xffffffffu, ssum, 4);
        if ((l & 7) == 0) atomicAdd(&g_sum[b * OO + o], ssum);
    }
}

// ============ K3: g_y[b][o][c] += sum_n exp(s[b,o,n]) * X[b,n,c]  (UNNORMALIZED) ====
#define CPAD3 136
#define WPAD 72
__global__ __launch_bounds__(256, 3) void k3_accum_mma(const float* __restrict__ X) {
    __shared__ __align__(16) __nv_bfloat16 Xhi3[64 * CPAD3];
    __shared__ __align__(16) __nv_bfloat16 Xlo3[64 * CPAD3];
    __shared__ __align__(16) __nv_bfloat16 Whi[OO * WPAD];
    __shared__ __align__(16) __nv_bfloat16 Wlo[OO * WPAD];

    int t = threadIdx.x, w = t >> 5, l = t & 31;
    int b = blockIdx.y;
    int ns = blockIdx.x >> 2;
    int cq = blockIdx.x & 3;
    int mh = w >> 2, wc = w & 3;

    float acc[4][4];
#pragma unroll
    for (int ct = 0; ct < 4; ct++)
#pragma unroll
        for (int j = 0; j < 4; j++) acc[ct][j] = 0.f;

    const float* Xb = X + (size_t)b * NN * DD + cq * 128;
    const float* Sb = g_S + (size_t)b * OO * NN;

    int lm_row = ((l >> 3) & 1) * 8 + (l & 7);
    int lm_col = (l >> 4) * 8;

    float4 xv[8], sv[2];
    auto load_stage = [&](int s) {
        int n0 = ns * 1024 + s * 64;
#pragma unroll
        for (int i = 0; i < 8; i++) {
            int idx = t + i * 256;
            int n = idx >> 5, qc = idx & 31;
            xv[i] = *(const float4*)(Xb + (size_t)(n0 + n) * DD + qc * 4);
        }
#pragma unroll
        for (int i = 0; i < 2; i++) {
            int idx = t + i * 256;
            int o = idx >> 4, q = idx & 15;
            sv[i] = *(const float4*)(Sb + (size_t)o * NN + n0 + q * 4);
        }
    };

    load_stage(0);

#pragma unroll 1
    for (int s = 0; s < 16; s++) {
        __syncthreads();
#pragma unroll
        for (int i = 0; i < 8; i++) {
            int idx = t + i * 256;
            int n = idx >> 5, qc = idx & 31;
            unsigned h0, l0, h1, l1;
            split2(xv[i].x, xv[i].y, h0, l0);
            split2(xv[i].z, xv[i].w, h1, l1);
            *(uint2*)(Xhi3 + n * CPAD3 + qc * 4) = make_uint2(h0, h1);
            *(uint2*)(Xlo3 + n * CPAD3 + qc * 4) = make_uint2(l0, l1);
        }
#pragma unroll
        for (int i = 0; i < 2; i++) {
            int idx = t + i * 256;
            int o = idx >> 4, q = idx & 15;
            unsigned h0, l0, h1, l1;
            split2(sv[i].x, sv[i].y, h0, l0);
            split2(sv[i].z, sv[i].w, h1, l1);
            *(uint2*)(Whi + o * WPAD + q * 4) = make_uint2(h0, h1);
            *(uint2*)(Wlo + o * WPAD + q * 4) = make_uint2(l0, l1);
        }
        __syncthreads();

        if (s + 1 < 16) load_stage(s + 1);

#pragma unroll
        for (int ks = 0; ks < 4; ks++) {
            int ar = (mh * 16 + (l >> 2)) * WPAD + ks * 16 + (l & 3) * 2;
            unsigned ah[4], al[4];
            ah[0] = *(const unsigned*)(Whi + ar);
            ah[1] = *(const unsigned*)(Whi + ar + 8 * WPAD);
            ah[2] = *(const unsigned*)(Whi + ar + 8);
            ah[3] = *(const unsigned*)(Whi + ar + 8 * WPAD + 8);
            al[0] = *(const unsigned*)(Wlo + ar);
            al[1] = *(const unsigned*)(Wlo + ar + 8 * WPAD);
            al[2] = *(const unsigned*)(Wlo + ar + 8);
            al[3] = *(const unsigned*)(Wlo + ar + 8 * WPAD + 8);
            int nr = (ks * 16 + lm_row) * CPAD3;
#pragma unroll
            for (int cp = 0; cp < 2; cp++) {
                int cc = wc * 32 + cp * 16 + lm_col;
                unsigned bh0, bh1, bh2, bh3, bl0, bl1, bl2, bl3;
                ldsm4t(bh0, bh1, bh2, bh3, Xhi3 + nr + cc);
                ldsm4t(bl0, bl1, bl2, bl3, Xlo3 + nr + cc);
                mma_bf16(acc[2 * cp],     ah, bh0, bh1);
                mma_bf16(acc[2 * cp],     ah, bl0, bl1);
                mma_bf16(acc[2 * cp],     al, bh0, bh1);
                mma_bf16(acc[2 * cp + 1], ah, bh2, bh3);
                mma_bf16(acc[2 * cp + 1], ah, bl2, bl3);
                mma_bf16(acc[2 * cp + 1], al, bh2, bh3);
            }
        }
    }

    // epilogue: atomic accumulate into g_y[b][o][cq*128 + col]
    int orow = mh * 16 + (l >> 2);
    float* yp = g_y + ((size_t)b * OO) * DD + cq * 128;
#pragma unroll
    for (int ct = 0; ct < 4; ct++) {
        int col = wc * 32 + (ct >> 1) * 16 + (ct & 1) * 8 + 2 * (l & 3);
        atomicAdd(&yp[(size_t)orow * DD + col],           acc[ct][0]);
        atomicAdd(&yp[(size_t)orow * DD + col + 1],       acc[ct][1]);
        atomicAdd(&yp[(size_t)(orow + 8) * DD + col],     acc[ct][2]);
        atomicAdd(&yp[(size_t)(orow + 8) * DD + col + 1], acc[ct][3]);
    }
}

// ---- K4a: split-K Wv stage, coalesced sub-warp GEMV. grid (8 kq, 64 bi). ----
// Normalization folded in here: ysl = g_y * (1/g_sum).
__global__ __launch_bounds__(256) void k4a_wv(const float* __restrict__ Wv) {
    __shared__ float ysl[HH * 64];
    int kq = blockIdx.x, bi = blockIdx.y;
    int b = bi >> 2, i = bi & 3;
    int t = threadIdx.x;

    if (t < 128) {
        int h = t >> 4, c4 = t & 15;     // 8 h x 16 float4
        int o = i * HH + h;
        float iv = 1.0f / g_sum[b * OO + o];
        float4 v = *(const float4*)(g_y + ((size_t)b * OO + o) * DD + kq * 64 + c4 * 4);
        ((float4*)ysl)[t] = make_float4(v.x * iv, v.y * iv, v.z * iv, v.w * iv);
    }
    __syncthreads();

    int w = t >> 5, l = t & 31;
    int grp = l >> 3, j = l & 7;
    const float4* yr = (const float4*)(ysl + w * 64);   // h == w

#pragma unroll 2
    for (int k = 0; k < 16; k++) {
        int g = w * 64 + k * 4 + grp;
        const float4* wr = (const float4*)(Wv + (size_t)g * DD + kq * 64);
        float acc = 0.f;
#pragma unroll
        for (int p = 0; p < 2; p++) {
            float4 w4 = wr[j + p * 8];
            float4 y4 = yr[j + p * 8];
            acc += w4.x * y4.x + w4.y * y4.y + w4.z * y4.z + w4.w * y4.w;
        }
        acc += __shfl_xor_sync(0xffffffffu, acc, 1);
        acc += __shfl_xor_sync(0xffffffffu, acc, 2);
        acc += __shfl_xor_sync(0xffffffffu, acc, 4);
        if (j == 0) atomicAdd(&g_pre[bi * DD + g], acc);
    }
}

// ---- K4b: split-K Wo stage, coalesced sub-warp GEMV. grid (8 kq, 64 bi). ----
__global__ __launch_bounds__(256) void k4b_wo(const float* __restrict__ Wo,
                                              const float* __restrict__ bv) {
    __shared__ float psl[64];
    int kq = blockIdx.x, bi = blockIdx.y;
    int t = threadIdx.x;
    if (t < 64) psl[t] = g_pre[bi * DD + kq * 64 + t] + bv[kq * 64 + t];
    __syncthreads();

    int w = t >> 5, l = t & 31;
    int grp = l >> 3, j = l & 7;
    const float4* pr = (const float4*)psl;

#pragma unroll 2
    for (int k = 0; k < 16; k++) {
        int g = w * 64 + k * 4 + grp;
        const float4* wr = (const float4*)(Wo + (size_t)g * DD + kq * 64);
        float acc = 0.f;
#pragma unroll
        for (int p = 0; p < 2; p++) {
            float4 w4 = wr[j + p * 8];
            float4 p4 = pr[j + p * 8];
            acc += w4.x * p4.x + w4.y * p4.y + w4.z * p4.z + w4.w * p4.w;
        }
        acc += __shfl_xor_sync(0xffffffffu, acc, 1);
        acc += __shfl_xor_sync(0xffffffffu, acc, 2);
        acc += __shfl_xor_sync(0xffffffffu, acc, 4);
        if (j == 0) atomicAdd(&g_z[bi * DD + g], acc);
    }
}

// ---- K4c: residual + LayerNorm + store. grid 64. ----
__global__ __launch_bounds__(256) void k4c_ln(const float* __restrict__ seed,
                                              const float* __restrict__ bo,
                                              const float* __restrict__ gamma,
                                              const float* __restrict__ beta,
                                              float* __restrict__ out) {
    __shared__ float red[256];
    int bi = blockIdx.x;
    int b = bi >> 2, i = bi & 3;
    int t = threadIdx.x;

    float zv[2];
#pragma unroll
    for (int gi = 0; gi < 2; gi++) {
        int g = t + gi * 256;
        zv[gi] = g_z[bi * DD + g] + bo[g] + seed[(size_t)i * DD + g];
    }

    red[t] = zv[0] + zv[1]; __syncthreads();
    for (int st = 128; st > 0; st >>= 1) { if (t < st) red[t] += red[t + st]; __syncthreads(); }
    float mu = red[0] * (1.0f / DD); __syncthreads();
    float d0 = zv[0] - mu, d1 = zv[1] - mu;
    red[t] = d0 * d0 + d1 * d1; __syncthreads();
    for (int st = 128; st > 0; st >>= 1) { if (t < st) red[t] += red[t + st]; __syncthreads(); }
    float rstd = rsqrtf(red[0] * (1.0f / DD) + 1e-6f);

    float* op = out + ((size_t)b * KSEED + i) * DD;
#pragma unroll
    for (int gi = 0; gi < 2; gi++) {
        int g = t + gi * 256;
        op[g] = (zv[gi] - mu) * rstd * gamma[g] + beta[g];
    }
}

extern "C" void kernel_launch(void* const* d_in, const int* in_sizes, int n_in,
                              void* d_out, int out_size) {
    const float* X     = (const float*)d_in[0];
    const float* seed  = (const float*)d_in[1];
    const float* Wq    = (const float*)d_in[2];
    const float* bq    = (const float*)d_in[3];
    const float* Wk    = (const float*)d_in[4];
    const float* bk    = (const float*)d_in[5];
    const float* Wv    = (const float*)d_in[6];
    const float* bv    = (const float*)d_in[7];
    const float* Wo    = (const float*)d_in[8];
    const float* bo    = (const float*)d_in[9];
    const float* gamma = (const float*)d_in[10];
    const float* beta  = (const float*)d_in[11];
    float* out = (float*)d_out;

    k0_fused<<<HH, 512>>>(seed, Wq, bq, Wk, bk);
    k1_scores_mma<<<dim3(NN / 128, BB), 256>>>(X);
    k3_accum_mma<<<dim3(32, BB), 256>>>(X);
    k4a_wv<<<dim3(8, BB * KSEED), 256>>>(Wv);
    k4b_wo<<<dim3(8, BB * KSEED), 256>>>(Wo, bv);
    k4c_ln<<<BB * KSEED, 256>>>(seed, bo, gamma, beta, out);
}

// round 17
// speedup vs baseline: 1.2163x; 1.2163x over previous
#include <cuda_runtime.h>
#include <cuda_bf16.h>
#include <math.h>
#include <stdint.h>

#define BB 16
#define NN 8192
#define DD 512
#define HH 8
#define KSEED 4
#define OO 32            // KSEED*HH, o = i*8 + h

// ---- scratch (no allocations allowed; __device__ globals) ----
__device__ float g_P[OO * DD];
__device__ float g_c0[OO];
__device__ float g_S[(size_t)BB * OO * NN];        // exp(scores)
__device__ float g_sum[BB * OO];                   // sum of exp (atomic)
__device__ float g_y[BB * OO * DD];                // UNNORMALIZED pooled values (atomic)
__device__ float g_pre[BB * KSEED * DD];           // Wv-stage output (atomic)
__device__ float g_z[BB * KSEED * DD];             // Wo-stage output (atomic)

// ---- warp-level bf16 MMA ----
__device__ __forceinline__ void mma_bf16(float* c, const unsigned* a,
                                         unsigned b0, unsigned b1) {
    asm volatile(
        "mma.sync.aligned.m16n8k16.row.col.f32.bf16.bf16.f32 "
        "{%0,%1,%2,%3}, {%4,%5,%6,%7}, {%8,%9}, {%0,%1,%2,%3};"
        : "+f"(c[0]), "+f"(c[1]), "+f"(c[2]), "+f"(c[3])
        : "r"(a[0]), "r"(a[1]), "r"(a[2]), "r"(a[3]), "r"(b0), "r"(b1));
}

__device__ __forceinline__ void ldsm4t(unsigned& r0, unsigned& r1,
                                       unsigned& r2, unsigned& r3,
                                       const void* p) {
    uint32_t a = (uint32_t)__cvta_generic_to_shared(p);
    asm volatile(
        "ldmatrix.sync.aligned.m8n8.x4.trans.shared.b16 {%0,%1,%2,%3}, [%4];"
        : "=r"(r0), "=r"(r1), "=r"(r2), "=r"(r3) : "r"(a));
}

__device__ __forceinline__ void split2(float a, float b, unsigned& hi, unsigned& lo) {
    __nv_bfloat16 ha = __float2bfloat16_rn(a), hb = __float2bfloat16_rn(b);
    unsigned uh = (unsigned)__bfloat16_as_ushort(ha) |
                  ((unsigned)__bfloat16_as_ushort(hb) << 16);
    __nv_bfloat16 la = __float2bfloat16_rn(a - __bfloat162float(ha));
    __nv_bfloat16 lb = __float2bfloat16_rn(b - __bfloat162float(hb));
    unsigned ul = (unsigned)__bfloat16_as_ushort(la) |
                  ((unsigned)__bfloat16_as_ushort(lb) << 16);
    hi = uh; lo = ul;
}

// ---- K0 (fused): per head h, compute q-slice, then P and c0; zero accumulators ----
__global__ void k0_fused(const float* __restrict__ seed,
                         const float* __restrict__ Wq,
                         const float* __restrict__ bq,
                         const float* __restrict__ Wk,
                         const float* __restrict__ bk) {
    __shared__ float qsh[KSEED * 64];
    int h = blockIdx.x;
    int t = threadIdx.x;
    if (t < BB * OO) g_sum[t] = 0.f;
    {
        int gid = t + h * 512;
        float4 z4 = make_float4(0.f, 0.f, 0.f, 0.f);
        for (int z = gid; z < BB * OO * DD / 4; z += HH * 512)
            ((float4*)g_y)[z] = z4;
        for (int z = gid; z < BB * KSEED * DD / 4; z += HH * 512) {
            ((float4*)g_pre)[z] = z4;
            ((float4*)g_z)[z] = z4;
        }
    }
    if (t < KSEED * 64) {
        int i = t >> 6, d = t & 63;
        int g = h * 64 + d;
        const float4* w  = (const float4*)(Wq + (size_t)g * DD);
        const float4* sd = (const float4*)(seed + (size_t)i * DD);
        float acc = 0.f;
#pragma unroll 8
        for (int e4 = 0; e4 < DD / 4; e4++) {
            float4 a = w[e4], s4 = sd[e4];
            acc += a.x * s4.x + a.y * s4.y + a.z * s4.z + a.w * s4.w;
        }
        qsh[t] = acc + bq[g];
    }
    __syncthreads();
    int c = t;   // 0..511
    float acc[KSEED] = {0.f, 0.f, 0.f, 0.f};
#pragma unroll 8
    for (int d = 0; d < 64; d++) {
        float w = Wk[(size_t)(h * 64 + d) * DD + c];
#pragma unroll
        for (int i = 0; i < KSEED; i++) acc[i] += qsh[i * 64 + d] * w;
    }
#pragma unroll
    for (int i = 0; i < KSEED; i++)
        g_P[(size_t)(i * HH + h) * DD + c] = acc[i] * 0.125f;
    if (c < KSEED) {
        float a = 0.f;
#pragma unroll 8
        for (int d = 0; d < 64; d++) a += qsh[c * 64 + d] * bk[h * 64 + d];
        g_c0[c * HH + h] = a * 0.125f;
    }
}

// ============ K1: exp-scores + per-(b,o) partial sums (atomic) ============
#define XP 72   // padded row (bf16 elements) for X tile
#define SCP 132 // scratch row pad (floats)
__global__ __launch_bounds__(256) void k1_scores_mma(const float* __restrict__ X) {
    __shared__ __align__(16) __nv_bfloat16 Xhi[128 * XP];   // reused as scratch
    __shared__ __align__(16) __nv_bfloat16 Xlo[128 * XP];
    __shared__ __align__(16) __nv_bfloat16 Phi[OO * XP];
    __shared__ __align__(16) __nv_bfloat16 Plo[OO * XP];
    __shared__ float c0s[OO];

    int t = threadIdx.x, w = t >> 5, l = t & 31;
    int b = blockIdx.y;
    int nbase = blockIdx.x * 128;
    if (t < OO) c0s[t] = g_c0[t];

    float acc[4][4];
#pragma unroll
    for (int ot = 0; ot < 4; ot++)
#pragma unroll
        for (int j = 0; j < 4; j++) acc[ot][j] = 0.f;

    const float* Xb = X + ((size_t)b * NN + nbase) * DD;

    float4 xv[8], pv[2];
    auto load_stage = [&](int kc) {
        int cbase = kc * 64;
#pragma unroll
        for (int i = 0; i < 8; i++) {
            int idx = t + i * 256;
            int row = idx >> 4, q = idx & 15;
            xv[i] = *(const float4*)(Xb + (size_t)row * DD + cbase + q * 4);
        }
#pragma unroll
        for (int i = 0; i < 2; i++) {
            int idx = t + i * 256;
            int row = idx >> 4, q = idx & 15;
            pv[i] = *(const float4*)(g_P + (size_t)row * DD + cbase + q * 4);
        }
    };

    load_stage(0);

#pragma unroll 1
    for (int kc = 0; kc < 8; kc++) {
        __syncthreads();
#pragma unroll
        for (int i = 0; i < 8; i++) {
            int idx = t + i * 256;
            int row = idx >> 4, q = idx & 15;
            unsigned h0, l0, h1, l1;
            split2(xv[i].x, xv[i].y, h0, l0);
            split2(xv[i].z, xv[i].w, h1, l1);
            *(uint2*)(Xhi + row * XP + q * 4) = make_uint2(h0, h1);
            *(uint2*)(Xlo + row * XP + q * 4) = make_uint2(l0, l1);
        }
#pragma unroll
        for (int i = 0; i < 2; i++) {
            int idx = t + i * 256;
            int row = idx >> 4, q = idx & 15;
            unsigned h0, l0, h1, l1;
            split2(pv[i].x, pv[i].y, h0, l0);
            split2(pv[i].z, pv[i].w, h1, l1);
            *(uint2*)(Phi + row * XP + q * 4) = make_uint2(h0, h1);
            *(uint2*)(Plo + row * XP + q * 4) = make_uint2(l0, l1);
        }
        __syncthreads();

        if (kc + 1 < 8) load_stage(kc + 1);

#pragma unroll
        for (int ks = 0; ks < 4; ks++) {
            int ar = (w * 16 + (l >> 2)) * XP + ks * 16 + (l & 3) * 2;
            unsigned ah[4], al[4];
            ah[0] = *(const unsigned*)(Xhi + ar);
            ah[1] = *(const unsigned*)(Xhi + ar + 8 * XP);
            ah[2] = *(const unsigned*)(Xhi + ar + 8);
            ah[3] = *(const unsigned*)(Xhi + ar + 8 * XP + 8);
            al[0] = *(const unsigned*)(Xlo + ar);
            al[1] = *(const unsigned*)(Xlo + ar + 8 * XP);
            al[2] = *(const unsigned*)(Xlo + ar + 8);
            al[3] = *(const unsigned*)(Xlo + ar + 8 * XP + 8);
#pragma unroll
            for (int ot = 0; ot < 4; ot++) {
                int br = (ot * 8 + (l >> 2)) * XP + ks * 16 + (l & 3) * 2;
                unsigned bh0 = *(const unsigned*)(Phi + br);
                unsigned bh1 = *(const unsigned*)(Phi + br + 8);
                unsigned bl0 = *(const unsigned*)(Plo + br);
                unsigned bl1 = *(const unsigned*)(Plo + br + 8);
                mma_bf16(acc[ot], ah, bh0, bh1);
                mma_bf16(acc[ot], ah, bl0, bl1);
                mma_bf16(acc[ot], al, bh0, bh1);
            }
        }
    }

    // ---- epilogue: exp, store, block-reduce sums, atomic ----
    __syncthreads();
    float* scratch = (float*)Xhi;
    int row = w * 16 + (l >> 2);
#pragma unroll
    for (int ot = 0; ot < 4; ot++) {
        int colb = ot * 8 + 2 * (l & 3);
#pragma unroll
        for (int j = 0; j < 4; j++) {
            int col = colb + (j & 1);
            int r2  = row + 8 * (j >> 1);
            float e = __expf(acc[ot][j] + c0s[col]);
            g_S[((size_t)b * OO + col) * NN + nbase + r2] = e;
            scratch[col * SCP + r2] = e;
        }
    }
    __syncthreads();
    {
        int o = w * 4 + (l >> 3);
        int nstart = (l & 7) * 16;
        const float* sr = scratch + o * SCP + nstart;
        float ssum = 0.f;
#pragma unroll
        for (int k = 0; k < 16; k++) ssum += sr[k];
        ssum += __shfl_xor_sync(0xffffffffu, ssum, 1);
        ssum += __shfl_xor_sync(0xffffffffu, ssum, 2);
        ssum += __shfl_xor_sync(0xffffffffu, ssum, 4);
        if ((l & 7) == 0) atomicAdd(&g_sum[b * OO + o], ssum);
    }
}

// ============ K3: g_y[b][o][c] += sum_n exp(s[b,o,n]) * X[b,n,c]  (UNNORMALIZED) ====
#define CPAD3 136
#define WPAD 72
__global__ __launch_bounds__(256) void k3_accum_mma(const float* __restrict__ X) {
    __shared__ __align__(16) __nv_bfloat16 Xhi3[64 * CPAD3];
    __shared__ __align__(16) __nv_bfloat16 Xlo3[64 * CPAD3];
    __shared__ __align__(16) __nv_bfloat16 Whi[OO * WPAD];
    __shared__ __align__(16) __nv_bfloat16 Wlo[OO * WPAD];

    int t = threadIdx.x, w = t >> 5, l = t & 31;
    int b = blockIdx.y;
    int ns = blockIdx.x >> 2;
    int cq = blockIdx.x & 3;
    int mh = w >> 2, wc = w & 3;

    float acc[4][4];
#pragma unroll
    for (int ct = 0; ct < 4; ct++)
#pragma unroll
        for (int j = 0; j < 4; j++) acc[ct][j] = 0.f;

    const float* Xb = X + (size_t)b * NN * DD + cq * 128;
    const float* Sb = g_S + (size_t)b * OO * NN;

    int lm_row = ((l >> 3) & 1) * 8 + (l & 7);
    int lm_col = (l >> 4) * 8;

    float4 xv[8], sv[2];
    auto load_stage = [&](int s) {
        int n0 = ns * 1024 + s * 64;
#pragma unroll
        for (int i = 0; i < 8; i++) {
            int idx = t + i * 256;
            int n = idx >> 5, qc = idx & 31;
            xv[i] = *(const float4*)(Xb + (size_t)(n0 + n) * DD + qc * 4);
        }
#pragma unroll
        for (int i = 0; i < 2; i++) {
            int idx = t + i * 256;
            int o = idx >> 4, q = idx & 15;
            sv[i] = *(const float4*)(Sb + (size_t)o * NN + n0 + q * 4);
        }
    };

    load_stage(0);

#pragma unroll 1
    for (int s = 0; s < 16; s++) {
        __syncthreads();
#pragma unroll
        for (int i = 0; i < 8; i++) {
            int idx = t + i * 256;
            int n = idx >> 5, qc = idx & 31;
            unsigned h0, l0, h1, l1;
            split2(xv[i].x, xv[i].y, h0, l0);
            split2(xv[i].z, xv[i].w, h1, l1);
            *(uint2*)(Xhi3 + n * CPAD3 + qc * 4) = make_uint2(h0, h1);
            *(uint2*)(Xlo3 + n * CPAD3 + qc * 4) = make_uint2(l0, l1);
        }
#pragma unroll
        for (int i = 0; i < 2; i++) {
            int idx = t + i * 256;
            int o = idx >> 4, q = idx & 15;
            unsigned h0, l0, h1, l1;
            split2(sv[i].x, sv[i].y, h0, l0);
            split2(sv[i].z, sv[i].w, h1, l1);
            *(uint2*)(Whi + o * WPAD + q * 4) = make_uint2(h0, h1);
            *(uint2*)(Wlo + o * WPAD + q * 4) = make_uint2(l0, l1);
        }
        __syncthreads();

        if (s + 1 < 16) load_stage(s + 1);

#pragma unroll
        for (int ks = 0; ks < 4; ks++) {
            int ar = (mh * 16 + (l >> 2)) * WPAD + ks * 16 + (l & 3) * 2;
            unsigned ah[4], al[4];
            ah[0] = *(const unsigned*)(Whi + ar);
            ah[1] = *(const unsigned*)(Whi + ar + 8 * WPAD);
            ah[2] = *(const unsigned*)(Whi + ar + 8);
            ah[3] = *(const unsigned*)(Whi + ar + 8 * WPAD + 8);
            al[0] = *(const unsigned*)(Wlo + ar);
            al[1] = *(const unsigned*)(Wlo + ar + 8 * WPAD);
            al[2] = *(const unsigned*)(Wlo + ar + 8);
            al[3] = *(const unsigned*)(Wlo + ar + 8 * WPAD + 8);
            int nr = (ks * 16 + lm_row) * CPAD3;
#pragma unroll
            for (int cp = 0; cp < 2; cp++) {
                int cc = wc * 32 + cp * 16 + lm_col;
                unsigned bh0, bh1, bh2, bh3, bl0, bl1, bl2, bl3;
                ldsm4t(bh0, bh1, bh2, bh3, Xhi3 + nr + cc);
                ldsm4t(bl0, bl1, bl2, bl3, Xlo3 + nr + cc);
                mma_bf16(acc[2 * cp],     ah, bh0, bh1);
                mma_bf16(acc[2 * cp],     ah, bl0, bl1);
                mma_bf16(acc[2 * cp],     al, bh0, bh1);
                mma_bf16(acc[2 * cp + 1], ah, bh2, bh3);
                mma_bf16(acc[2 * cp + 1], ah, bl2, bl3);
                mma_bf16(acc[2 * cp + 1], al, bh2, bh3);
            }
        }
    }

    // epilogue: atomic accumulate into g_y[b][o][cq*128 + col]
    int orow = mh * 16 + (l >> 2);
    float* yp = g_y + ((size_t)b * OO) * DD + cq * 128;
#pragma unroll
    for (int ct = 0; ct < 4; ct++) {
        int col = wc * 32 + (ct >> 1) * 16 + (ct & 1) * 8 + 2 * (l & 3);
        atomicAdd(&yp[(size_t)orow * DD + col],           acc[ct][0]);
        atomicAdd(&yp[(size_t)orow * DD + col + 1],       acc[ct][1]);
        atomicAdd(&yp[(size_t)(orow + 8) * DD + col],     acc[ct][2]);
        atomicAdd(&yp[(size_t)(orow + 8) * DD + col + 1], acc[ct][3]);
    }
}

// ---- K4a: split-K Wv stage, coalesced sub-warp GEMV. grid (4 kq, 64 bi). ----
// Normalization folded in: ysl = g_y * (1/g_sum).
__global__ __launch_bounds__(256) void k4a_wv(const float* __restrict__ Wv) {
    __shared__ float ysl[HH * 128];
    int kq = blockIdx.x, bi = blockIdx.y;
    int b = bi >> 2, i = bi & 3;
    int t = threadIdx.x;

    {
        int h = t >> 5, c4 = t & 31;     // 8 h x 32 float4
        int o = i * HH + h;
        float iv = 1.0f / g_sum[b * OO + o];
        float4 v = *(const float4*)(g_y + ((size_t)b * OO + o) * DD + kq * 128 + c4 * 4);
        ((float4*)ysl)[t] = make_float4(v.x * iv, v.y * iv, v.z * iv, v.w * iv);
    }
    __syncthreads();

    int w = t >> 5, l = t & 31;
    int grp = l >> 3, j = l & 7;
    const float4* yr = (const float4*)(ysl + w * 128);   // h == w

#pragma unroll 2
    for (int k = 0; k < 16; k++) {
        int g = w * 64 + k * 4 + grp;
        const float4* wr = (const float4*)(Wv + (size_t)g * DD + kq * 128);
        float acc = 0.f;
#pragma unroll
        for (int p = 0; p < 4; p++) {
            float4 w4 = wr[j + p * 8];
            float4 y4 = yr[j + p * 8];
            acc += w4.x * y4.x + w4.y * y4.y + w4.z * y4.z + w4.w * y4.w;
        }
        acc += __shfl_xor_sync(0xffffffffu, acc, 1);
        acc += __shfl_xor_sync(0xffffffffu, acc, 2);
        acc += __shfl_xor_sync(0xffffffffu, acc, 4);
        if (j == 0) atomicAdd(&g_pre[bi * DD + g], acc);
    }
}

// ---- K4b: split-K Wo stage, coalesced sub-warp GEMV. grid (8 kq, 64 bi). ----
__global__ __launch_bounds__(256) void k4b_wo(const float* __restrict__ Wo,
                                              const float* __restrict__ bv) {
    __shared__ float psl[64];
    int kq = blockIdx.x, bi = blockIdx.y;
    int t = threadIdx.x;
    if (t < 64) psl[t] = g_pre[bi * DD + kq * 64 + t] + bv[kq * 64 + t];
    __syncthreads();

    int w = t >> 5, l = t & 31;
    int grp = l >> 3, j = l & 7;
    const float4* pr = (const float4*)psl;

#pragma unroll 2
    for (int k = 0; k < 16; k++) {
        int g = w * 64 + k * 4 + grp;
        const float4* wr = (const float4*)(Wo + (size_t)g * DD + kq * 64);
        float acc = 0.f;
#pragma unroll
        for (int p = 0; p < 2; p++) {
            float4 w4 = wr[j + p * 8];
            float4 p4 = pr[j + p * 8];
            acc += w4.x * p4.x + w4.y * p4.y + w4.z * p4.z + w4.w * p4.w;
        }
        acc += __shfl_xor_sync(0xffffffffu, acc, 1);
        acc += __shfl_xor_sync(0xffffffffu, acc, 2);
        acc += __shfl_xor_sync(0xffffffffu, acc, 4);
        if (j == 0) atomicAdd(&g_z[bi * DD + g], acc);
    }
}

// ---- K4c: residual + LayerNorm + store. grid 64. ----
__global__ __launch_bounds__(256) void k4c_ln(const float* __restrict__ seed,
                                              const float* __restrict__ bo,
                                              const float* __restrict__ gamma,
                                              const float* __restrict__ beta,
                                              float* __restrict__ out) {
    __shared__ float red[256];
    int bi = blockIdx.x;
    int b = bi >> 2, i = bi & 3;
    int t = threadIdx.x;

    float zv[2];
#pragma unroll
    for (int gi = 0; gi < 2; gi++) {
        int g = t + gi * 256;
        zv[gi] = g_z[bi * DD + g] + bo[g] + seed[(size_t)i * DD + g];
    }

    red[t] = zv[0] + zv[1]; __syncthreads();
    for (int st = 128; st > 0; st >>= 1) { if (t < st) red[t] += red[t + st]; __syncthreads(); }
    float mu = red[0] * (1.0f / DD); __syncthreads();
    float d0 = zv[0] - mu, d1 = zv[1] - mu;
    red[t] = d0 * d0 + d1 * d1; __syncthreads();
    for (int st = 128; st > 0; st >>= 1) { if (t < st) red[t] += red[t + st]; __syncthreads(); }
    float rstd = rsqrtf(red[0] * (1.0f / DD) + 1e-6f);

    float* op = out + ((size_t)b * KSEED + i) * DD;
#pragma unroll
    for (int gi = 0; gi < 2; gi++) {
        int g = t + gi * 256;
        op[g] = (zv[gi] - mu) * rstd * gamma[g] + beta[g];
    }
}

extern "C" void kernel_launch(void* const* d_in, const int* in_sizes, int n_in,
                              void* d_out, int out_size) {
    const float* X     = (const float*)d_in[0];
    const float* seed  = (const float*)d_in[1];
    const float* Wq    = (const float*)d_in[2];
    const float* bq    = (const float*)d_in[3];
    const float* Wk    = (const float*)d_in[4];
    const float* bk    = (const float*)d_in[5];
    const float* Wv    = (const float*)d_in[6];
    const float* bv    = (const float*)d_in[7];
    const float* Wo    = (const float*)d_in[8];
    const float* bo    = (const float*)d_in[9];
    const float* gamma = (const float*)d_in[10];
    const float* beta  = (const float*)d_in[11];
    float* out = (float*)d_out;

    k0_fused<<<HH, 512>>>(seed, Wq, bq, Wk, bk);
    k1_scores_mma<<<dim3(NN / 128, BB), 256>>>(X);
    k3_accum_mma<<<dim3(32, BB), 256>>>(X);
    k4a_wv<<<dim3(4, BB * KSEED), 256>>>(Wv);
    k4b_wo<<<dim3(8, BB * KSEED), 256>>>(Wo, bv);
    k4c_ln<<<BB * KSEED, 256>>>(seed, bo, gamma, beta, out);
}